// round 11
// baseline (speedup 1.0000x reference)
#include <cuda_runtime.h>
#include <cstdint>
#define DI __device__ __forceinline__

__device__ float g_p [8192*128];
__device__ float g_v [8192*128];
__device__ float g_P1[8192*128];
__device__ float g_V1[8192*128];
__device__ float g_Wfp[128*128];
__device__ float g_Wfv[128*128];
__device__ float g_biasF[2*128];
// tf32 fragment packs for pv prologue (k32 slabs, stride 36)
__device__ __align__(16) unsigned g_Wpf [4*4608];
__device__ __align__(16) unsigned g_Wfpf[4*4608];
__device__ __align__(16) unsigned g_Wvf [4*4608];
__device__ __align__(16) unsigned g_Wfvf[4*4608];
// fp16 fragment packs for main kernel (k64 slabs, stride 36)
__device__ __align__(16) unsigned g_W1h[4*4608];   // W1c|W1d rows 256..511
__device__ __align__(16) unsigned g_W2h[2*4608];

DI unsigned f2tf(float x){ unsigned r; asm("cvt.rna.tf32.f32 %0, %1;":"=r"(r):"f"(x)); return r; }
DI unsigned pk2(float lo, float hi){
    unsigned r;
    asm("cvt.rn.f16x2.f32 %0, %1, %2;" : "=r"(r) : "f"(hi), "f"(lo));
    return r;
}
DI void mma8(float* c, unsigned a0,unsigned a1,unsigned a2,unsigned a3,unsigned b0,unsigned b1){
    asm volatile("mma.sync.aligned.m16n8k8.row.col.f32.tf32.tf32.f32 "
        "{%0,%1,%2,%3},{%4,%5,%6,%7},{%8,%9},{%0,%1,%2,%3};\n"
        :"+f"(c[0]),"+f"(c[1]),"+f"(c[2]),"+f"(c[3])
        :"r"(a0),"r"(a1),"r"(a2),"r"(a3),"r"(b0),"r"(b1)); }
DI void mma16(float* c, unsigned a0,unsigned a1,unsigned a2,unsigned a3,unsigned b0,unsigned b1){
    asm volatile("mma.sync.aligned.m16n8k16.row.col.f32.f16.f16.f32 "
        "{%0,%1,%2,%3},{%4,%5,%6,%7},{%8,%9},{%0,%1,%2,%3};\n"
        :"+f"(c[0]),"+f"(c[1]),"+f"(c[2]),"+f"(c[3])
        :"r"(a0),"r"(a1),"r"(a2),"r"(a3),"r"(b0),"r"(b1)); }
DI void cp16(uint32_t s,const void* g){ asm volatile("cp.async.cg.shared.global [%0], [%1], 16;\n"::"r"(s),"l"(g)); }
DI void cpcommit(){ asm volatile("cp.async.commit_group;\n"); }
template<int N> DI void cpwait(){ asm volatile("cp.async.wait_group %0;\n"::"n"(N)); }
DI uint32_t s2u(const void* p){ uint32_t a; asm("{ .reg .u64 t; cvta.to.shared.u64 t, %1; cvt.u32.u64 %0, t; }":"=r"(a):"l"(p)); return a; }

// tf32 slab mma for pv kernel (unchanged, proven)
DI void mma_slab(float (*acc)[16][4], const unsigned* Ab, const unsigned* Wb, int lane){
#pragma unroll
    for(int ks=0; ks<4; ks++){
        unsigned a[2][4];
#pragma unroll
        for(int mi=0; mi<2; mi++){
            int c0 = ks*8 + mi*2;
            a[mi][0]=Ab[(c0+0)*32+lane]; a[mi][1]=Ab[(c0+1)*32+lane];
            a[mi][2]=Ab[(c0+4)*32+lane]; a[mi][3]=Ab[(c0+5)*32+lane];
        }
        const uint4* bb = (const uint4*)(Wb + (ks*32+lane)*36);
#pragma unroll
        for(int jj=0; jj<8; jj++){
            uint4 b = bb[jj];
            mma8(acc[0][2*jj],  a[0][0],a[0][1],a[0][2],a[0][3],b.x,b.y);
            mma8(acc[1][2*jj],  a[1][0],a[1][1],a[1][2],a[1][3],b.x,b.y);
            mma8(acc[0][2*jj+1],a[0][0],a[0][1],a[0][2],a[0][3],b.z,b.w);
            mma8(acc[1][2*jj+1],a[1][0],a[1][1],a[1][2],a[1][3],b.z,b.w);
        }
    }
}

__global__ __launch_bounds__(256) void prep_kernel(
    const float* __restrict__ Wp, const float* __restrict__ bp,
    const float* __restrict__ Wv, const float* __restrict__ bv,
    const float* __restrict__ W1){
    __shared__ float Wc_s[32*128];
    __shared__ float Wr_s[16*128];
    int cb = blockIdx.x, isv = cb>=8, rb = (cb&7)*16;
    const float* Wx  = isv? Wv: Wp;
    const float* W1x = W1 + (isv? 128*128: 0);
    float* outW = isv? g_Wfv: g_Wfp;
    int t = threadIdx.x;
    for(int i=t; i<16*128; i+=256) Wr_s[i] = Wx[(rb+(i>>7))*128 + (i&127)];
    float acc[8];
#pragma unroll
    for(int ii=0; ii<8; ii++) acc[ii]=0.f;
    int j = t&127, ih = (t>>7)*8;
    for(int kc=0; kc<4; kc++){
        __syncthreads();
        for(int i=t; i<32*128; i+=256) Wc_s[i] = W1x[(kc*32+(i>>7))*128 + (i&127)];
        __syncthreads();
        for(int k=0; k<32; k++){
            float b = Wc_s[k*128+j];
#pragma unroll
            for(int ii=0; ii<8; ii++) acc[ii] += Wr_s[(ih+ii)*128 + kc*32+k]*b;
        }
    }
#pragma unroll
    for(int ii=0; ii<8; ii++) outW[(rb+ih+ii)*128 + j] = acc[ii];
    if((cb&7)==0 && t<128){
        const float* bx = isv? bv: bp;
        float s=0.f;
        for(int k=0;k<128;k++) s += bx[k]*W1x[k*128+t];
        g_biasF[isv*128+t] = s;
    }
}

__global__ __launch_bounds__(128) void pack_kernel(
    const float* __restrict__ Wp, const float* __restrict__ Wv){
    int sid = blockIdx.x;
    const float* src; unsigned* dst;
    if      (sid<4) { src = Wp + sid*32*128;          dst = g_Wpf  + sid*4608; }
    else if (sid<8) { src = g_Wfp + (sid-4)*32*128;   dst = g_Wfpf + (sid-4)*4608; }
    else if (sid<12){ src = Wv + (sid-8)*32*128;      dst = g_Wvf  + (sid-8)*4608; }
    else            { src = g_Wfv + (sid-12)*32*128;  dst = g_Wfvf + (sid-12)*4608; }
    int t=threadIdx.x, lane=t&31, ks=t>>5, gid=lane>>2, t4=lane&3;
#pragma unroll
    for(int j=0;j<16;j++)
#pragma unroll
        for(int r=0;r<2;r++)
            dst[(ks*32+lane)*36 + 2*j + r] = f2tf(src[(ks*8+t4+r*4)*128 + j*8 + gid]);
}

// fp16 fragment pack for main-kernel weights. grid 6 x 128.
__global__ __launch_bounds__(128) void pack16_kernel(
    const float* __restrict__ W1, const float* __restrict__ W2){
    int sid = blockIdx.x;
    const float* src; unsigned* dst;
    if(sid<4){ src = W1 + (256 + sid*64)*128; dst = g_W1h + sid*4608; }
    else     { src = W2 + (sid-4)*64*128;     dst = g_W2h + (sid-4)*4608; }
    int t=threadIdx.x, lane=t&31, ks=t>>5, gid=lane>>2, t4=lane&3;
#pragma unroll
    for(int j=0;j<16;j++)
#pragma unroll
        for(int r=0;r<2;r++){
            int k0 = ks*16 + 2*t4 + 8*r;
            dst[(ks*32+lane)*36 + 2*j + r] =
                pk2(src[k0*128 + 8*j + gid], src[(k0+1)*128 + 8*j + gid]);
        }
}

__global__ __launch_bounds__(256) void pv_kernel(
    const float* __restrict__ price, const float* __restrict__ liquid,
    const float* __restrict__ bp, const float* __restrict__ bv){
    extern __shared__ float smpv[];
    unsigned* W_s = (unsigned*)smpv;
    unsigned* A_f = (unsigned*)smpv + 9216;
    float* bias_s = smpv + 13312;
    int cb=blockIdx.x, isv=cb>=64, rb=(cb&63)*128;
    const float* in = (isv? liquid: price) + (size_t)rb*128;
    const unsigned* pA = isv? g_Wvf : g_Wpf;
    const unsigned* pB = isv? g_Wfvf: g_Wfpf;
    float* outA = (isv? g_v : g_p)  + (size_t)rb*128;
    float* outB = (isv? g_V1: g_P1) + (size_t)rb*128;
    int t=threadIdx.x, w=t>>5, lane=t&31, gid=lane>>2, t4=lane&3;
    if(t<128) bias_s[t] = isv? bv[t]: bp[t];
    else      bias_s[t] = g_biasF[isv*128 + (t-128)];
    uint32_t Wsa = s2u(W_s);
    int sub=((t&31)>>4)*2 + ((t&15)>>3), gid4=(t&7)*4, bgrp=(t>>5)*1024;
    int rowgrp=w&3, pk=w>>2;
    float acc[2][16][4];
#pragma unroll
    for(int mi=0;mi<2;mi++)
#pragma unroll
        for(int j=0;j<16;j++)
#pragma unroll
            for(int e=0;e<4;e++) acc[mi][j][e]=0.f;
    for(int s=0;s<4;s++){
        if(s) __syncthreads();
        for(int i=t;i<2304;i+=256){
            const void* src = (i<1152)? (const void*)((const uint4*)(pA+s*4608)+i)
                                      : (const void*)((const uint4*)(pB+s*4608)+(i-1152));
            cp16(Wsa + i*16, src);
        }
        cpcommit();
        if(t<128){
            const float4* row = (const float4*)(in + (size_t)t*128 + s*32);
#pragma unroll
            for(int g=0;g<8;g++){
                float4 a=row[g];
                uint4 o={f2tf(a.x),f2tf(a.y),f2tf(a.z),f2tf(a.w)};
                *(uint4*)&A_f[bgrp + (g*4+sub)*32 + gid4] = o;
            }
        }
        cpwait<0>();
        __syncthreads();
        mma_slab(acc, A_f + rowgrp*1024, W_s + pk*4608, lane);
    }
    float* outX = pk? outB: outA;
#pragma unroll
    for(int mi=0;mi<2;mi++){
        int r0 = rowgrp*32 + mi*16 + gid;
#pragma unroll
        for(int j=0;j<16;j++){
            int c=j*8+2*t4;
            float b0=bias_s[pk*128+c], b1=bias_s[pk*128+c+1];
            *(float2*)&outX[(size_t)r0*128+c]     = make_float2(acc[mi][j][0]+b0, acc[mi][j][1]+b1);
            *(float2*)&outX[(size_t)(r0+8)*128+c] = make_float2(acc[mi][j][2]+b0, acc[mi][j][3]+b1);
        }
    }
}

// ---------------------------------------------------------------------------
// pair_main v2: 512 thr / 16 warps. warp = (rg = w>>1: 16 rows, ch = w&1: 64 cols)
// acc[8][4] = 32 regs. GEMM1 A built per-ks in regs; h staged fp16 in smem
// (conflict-free stride-68 u32), GEMM2 A re-read from h. 3-slot W ring.
// smem u32 layout: Wbuf[0,13824) b1@13824 b2@13952 V1@14080(32x136)
//   P1@18432(4x136) | alias zone: v@18976(32x136) p@23328(4x136)
//   h_u aliases [18976, 27680) = 128x68.  Total 110720 B -> 2 CTAs/SM.
// ---------------------------------------------------------------------------
DI void buildA1(unsigned ah[4], const float* pw, const float* v0, const float* v1,
                int s, int ks){
    int ko = (s&1)*64 + ks*16;
    float2 pl = *(const float2*)&pw[ko];
    float2 ph = *(const float2*)&pw[ko+8];
    float2 a0=*(const float2*)&v0[ko],   c0=*(const float2*)&v1[ko];
    float2 a1=*(const float2*)&v0[ko+8], c1=*(const float2*)&v1[ko+8];
    if(s<2){
        ah[0]=pk2(pl.x*a0.x, pl.y*a0.y);
        ah[1]=pk2(pl.x*c0.x, pl.y*c0.y);
        ah[2]=pk2(ph.x*a1.x, ph.y*a1.y);
        ah[3]=pk2(ph.x*c1.x, ph.y*c1.y);
    }else{
        ah[0]=pk2(fabsf(pl.x-a0.x), fabsf(pl.y-a0.y));
        ah[1]=pk2(fabsf(pl.x-c0.x), fabsf(pl.y-c0.y));
        ah[2]=pk2(fabsf(ph.x-a1.x), fabsf(ph.y-a1.y));
        ah[3]=pk2(fabsf(ph.x-c1.x), fabsf(ph.y-c1.y));
    }
}

DI void g1slab(float (*acc)[4], const float* pw, const float* v0, const float* v1,
               const unsigned* Wb, int lane, int ch, int s){
#pragma unroll
    for(int ks=0;ks<4;ks++){
        unsigned ah[4];
        buildA1(ah, pw, v0, v1, s, ks);
        const uint4* bb = (const uint4*)(Wb + (ks*32+lane)*36 + 16*ch);
#pragma unroll
        for(int jj=0;jj<4;jj++){
            uint4 b = bb[jj];
            mma16(acc[2*jj],  ah[0],ah[1],ah[2],ah[3],b.x,b.y);
            mma16(acc[2*jj+1],ah[0],ah[1],ah[2],ah[3],b.z,b.w);
        }
    }
}

DI void g2slab(float (*acc)[4], const unsigned* h0, const unsigned* h1,
               const unsigned* Wb, int lane, int ch, int s2){
#pragma unroll
    for(int ks=0;ks<4;ks++){
        int ksg = s2*4+ks;
        unsigned a0 = h0[8*ksg];
        unsigned a1 = h1[8*ksg];
        unsigned a2 = h0[8*ksg+4];
        unsigned a3 = h1[8*ksg+4];
        const uint4* bb = (const uint4*)(Wb + (ks*32+lane)*36 + 16*ch);
#pragma unroll
        for(int jj=0;jj<4;jj++){
            uint4 b = bb[jj];
            mma16(acc[2*jj],  a0,a1,a2,a3,b.x,b.y);
            mma16(acc[2*jj+1],a0,a1,a2,a3,b.z,b.w);
        }
    }
}

__global__ __launch_bounds__(512,2) void pair_main_kernel(
    const float* __restrict__ b1v, const float* __restrict__ b2v,
    float* __restrict__ out){
    extern __shared__ float sm[];
    unsigned* Wbuf = (unsigned*)sm;
    float* b1_s = sm + 13824;
    float* b2_s = sm + 13952;
    float* V1_s = sm + 14080;
    float* P1_s = sm + 18432;
    float* v_s  = sm + 18976;
    float* p_s  = sm + 23328;
    unsigned* h_u = (unsigned*)(sm + 18976);   // aliases v_s/p_s after GEMM1
    const int bt=blockIdx.x>>3, pb=blockIdx.x&7;
    const int t=threadIdx.x, w=t>>5, lane=t&31;
    const int gid=lane>>2, t4=lane&3;
    const int rg=w>>1, ch=w&1;
    const int n=rg>>1, mb=(rg&1)*16;
    uint32_t Wba = s2u(Wbuf);

    // pre-issue W1 slab0 -> slot0, slab1 -> slot1
    for(int i=t;i<1152;i+=512) cp16(Wba+i*16, (const uint4*)g_W1h+i);
    cpcommit();
    for(int i=t;i<1152;i+=512) cp16(Wba+18432+i*16, (const uint4*)(g_W1h+4608)+i);
    cpcommit();
    {   // tiles
        const float4* vg  = (const float4*)(g_v  + (size_t)bt*4096);
        const float4* V1g = (const float4*)(g_V1 + (size_t)bt*4096);
        for(int i=t;i<1024;i+=512){
            int m=i>>5, k4=(i&31)*4;
            *(float4*)&v_s [m*136+k4] = vg[i];
            *(float4*)&V1_s[m*136+k4] = V1g[i];
        }
        if(t<128){
            const float4* pg  = (const float4*)(g_p  + (size_t)(bt*32+pb*4)*128);
            const float4* P1g = (const float4*)(g_P1 + (size_t)(bt*32+pb*4)*128);
            int nn=t>>5, k4=(t&31)*4;
            *(float4*)&p_s [nn*136+k4] = pg[t];
            *(float4*)&P1_s[nn*136+k4] = P1g[t];
            b1_s[t]=b1v[t]; b2_s[t]=b2v[t];
        }
    }

    const float* pw = p_s + n*136 + 2*t4;
    const float* v0 = v_s + (mb+gid)*136 + 2*t4;
    const float* v1 = v0 + 8*136;

    float acc[8][4];
#pragma unroll
    for(int j=0;j<8;j++)
#pragma unroll
        for(int e=0;e<4;e++) acc[j][e]=0.f;

    // it0: slab0 (slot0); prefetch W1s2 -> slot2
    cpwait<1>(); __syncthreads();
    for(int i=t;i<1152;i+=512) cp16(Wba+2*18432+i*16, (const uint4*)(g_W1h+2*4608)+i);
    cpcommit();
    g1slab(acc, pw, v0, v1, Wbuf, lane, ch, 0);
    // it1: slab1 (slot1); prefetch W1s3 -> slot0
    cpwait<1>(); __syncthreads();
    for(int i=t;i<1152;i+=512) cp16(Wba+i*16, (const uint4*)(g_W1h+3*4608)+i);
    cpcommit();
    g1slab(acc, pw, v0, v1, Wbuf+4608, lane, ch, 1);
    // it2: slab2 (slot2); prefetch W2s0 -> slot1
    cpwait<1>(); __syncthreads();
    for(int i=t;i<1152;i+=512) cp16(Wba+18432+i*16, (const uint4*)g_W2h+i);
    cpcommit();
    g1slab(acc, pw, v0, v1, Wbuf+2*4608, lane, ch, 2);
    // it3: slab3 (slot0); prefetch W2s1 -> slot2
    cpwait<1>(); __syncthreads();
    for(int i=t;i<1152;i+=512) cp16(Wba+2*18432+i*16, (const uint4*)(g_W2h+4608)+i);
    cpcommit();
    g1slab(acc, pw, v0, v1, Wbuf, lane, ch, 3);

    // it4: W2s0 ready; all GEMM1 reads done -> v_s/p_s free for h alias
    cpwait<1>(); __syncthreads();
    {   // epilogue 1: silu(D + P1 + V1 + b1) -> h (fp16, smem)
        const float* P1p = P1_s + n*136;
        const float* V0p = V1_s + (mb+gid)*136;
        const float* V1p = V0p + 8*136;
        unsigned* h0 = h_u + (rg*16+gid)*68 + ch*32 + t4;
        unsigned* h1 = h0 + 8*68;
#pragma unroll
        for(int j=0;j<8;j++){
            int c = ch*64 + j*8 + 2*t4;
            float2 P  = *(const float2*)&P1p[c];
            float2 Bb = *(const float2*)&b1_s[c];
            float2 Va = *(const float2*)&V0p[c];
            float2 Vb = *(const float2*)&V1p[c];
            float x0=acc[j][0]+P.x+Va.x+Bb.x;
            float x1=acc[j][1]+P.y+Va.y+Bb.y;
            float x2=acc[j][2]+P.x+Vb.x+Bb.x;
            float x3=acc[j][3]+P.y+Vb.y+Bb.y;
            x0=x0/(1.f+__expf(-x0)); x1=x1/(1.f+__expf(-x1));
            x2=x2/(1.f+__expf(-x2)); x3=x3/(1.f+__expf(-x3));
            h0[4*j] = pk2(x0,x1);
            h1[4*j] = pk2(x2,x3);
            acc[j][0]=0.f; acc[j][1]=0.f; acc[j][2]=0.f; acc[j][3]=0.f;
        }
    }
    __syncthreads();   // publish h

    const unsigned* h0r = h_u + (rg*16+gid)*68 + t4;
    const unsigned* h1r = h0r + 8*68;
    // GEMM2 slab0 (slot1)
    g2slab(acc, h0r, h1r, Wbuf+4608, lane, ch, 0);
    // it5: GEMM2 slab1 (slot2)
    cpwait<0>(); __syncthreads();
    g2slab(acc, h0r, h1r, Wbuf+2*4608, lane, ch, 1);

    // epilogue 2: + b2, direct stores
    const size_t ob = (size_t)blockIdx.x*16384;
    float* o0 = out + ob + (size_t)(rg*16+gid)*128 + ch*64;
    float* o1 = o0 + 8*128;
#pragma unroll
    for(int j=0;j<8;j++){
        int c = j*8 + 2*t4;
        int cg = ch*64 + c;
        *(float2*)&o0[c] = make_float2(acc[j][0]+b2_s[cg], acc[j][1]+b2_s[cg+1]);
        *(float2*)&o1[c] = make_float2(acc[j][2]+b2_s[cg], acc[j][3]+b2_s[cg+1]);
    }
}

extern "C" void kernel_launch(void* const* d_in, const int* in_sizes, int n_in,
                              void* d_out, int out_size){
    const float* price =(const float*)d_in[0];
    const float* liquid=(const float*)d_in[1];
    const float* W_p=(const float*)d_in[2];
    const float* b_p=(const float*)d_in[3];
    const float* W_v=(const float*)d_in[4];
    const float* b_v=(const float*)d_in[5];
    const float* W1 =(const float*)d_in[6];
    const float* b1 =(const float*)d_in[7];
    const float* W2 =(const float*)d_in[8];
    const float* b2 =(const float*)d_in[9];
    float* out=(float*)d_out;
    cudaFuncSetAttribute(pv_kernel, cudaFuncAttributeMaxDynamicSharedMemorySize, 55296);
    cudaFuncSetAttribute(pair_main_kernel, cudaFuncAttributeMaxDynamicSharedMemorySize, 110720);
    prep_kernel<<<16, 256>>>(W_p, b_p, W_v, b_v, W1);
    pack_kernel<<<16, 128>>>(W_p, W_v);
    pack16_kernel<<<6, 128>>>(W1, W2);
    pv_kernel<<<128, 256, 54272>>>(price, liquid, b_p, b_v);
    pair_main_kernel<<<2048, 512, 110720>>>(b1, b2, out);
}

// round 12
// speedup vs baseline: 1.1248x; 1.1248x over previous
#include <cuda_runtime.h>
#include <cstdint>
#define DI __device__ __forceinline__

__device__ float g_p [8192*128];
__device__ float g_v [8192*128];
__device__ float g_P1[8192*128];
__device__ float g_V1[8192*128];
__device__ float g_Wfp[128*128];
__device__ float g_Wfv[128*128];
__device__ float g_biasF[2*128];
// tf32 fragment packs for pv prologue (k32 slabs, stride 36)
__device__ __align__(16) unsigned g_Wpf [4*4608];
__device__ __align__(16) unsigned g_Wfpf[4*4608];
__device__ __align__(16) unsigned g_Wvf [4*4608];
__device__ __align__(16) unsigned g_Wfvf[4*4608];
// fp16 fragment packs for main kernel (k64 slabs, stride 36)
__device__ __align__(16) unsigned g_W1h[4*4608];   // W1c|W1d rows 256..511
__device__ __align__(16) unsigned g_W2h[2*4608];

DI unsigned f2tf(float x){ unsigned r; asm("cvt.rna.tf32.f32 %0, %1;":"=r"(r):"f"(x)); return r; }
DI unsigned pk2(float lo, float hi){
    unsigned r;
    asm("cvt.rn.f16x2.f32 %0, %1, %2;" : "=r"(r) : "f"(hi), "f"(lo));
    return r;
}
DI void mma8(float* c, unsigned a0,unsigned a1,unsigned a2,unsigned a3,unsigned b0,unsigned b1){
    asm volatile("mma.sync.aligned.m16n8k8.row.col.f32.tf32.tf32.f32 "
        "{%0,%1,%2,%3},{%4,%5,%6,%7},{%8,%9},{%0,%1,%2,%3};\n"
        :"+f"(c[0]),"+f"(c[1]),"+f"(c[2]),"+f"(c[3])
        :"r"(a0),"r"(a1),"r"(a2),"r"(a3),"r"(b0),"r"(b1)); }
DI void mma16(float* c, unsigned a0,unsigned a1,unsigned a2,unsigned a3,unsigned b0,unsigned b1){
    asm volatile("mma.sync.aligned.m16n8k16.row.col.f32.f16.f16.f32 "
        "{%0,%1,%2,%3},{%4,%5,%6,%7},{%8,%9},{%0,%1,%2,%3};\n"
        :"+f"(c[0]),"+f"(c[1]),"+f"(c[2]),"+f"(c[3])
        :"r"(a0),"r"(a1),"r"(a2),"r"(a3),"r"(b0),"r"(b1)); }
DI uint32_t s2u(const void* p){ uint32_t a; asm("{ .reg .u64 t; cvta.to.shared.u64 t, %1; cvt.u32.u64 %0, t; }":"=r"(a):"l"(p)); return a; }

// ---- bulk async copy (UBLKCP) + mbarrier ----
DI void bulkcp(uint32_t dst, const void* src, uint32_t bytes, uint32_t mbar){
    asm volatile("cp.async.bulk.shared::cta.global.mbarrier::complete_tx::bytes [%0], [%1], %2, [%3];"
                 :: "r"(dst), "l"(src), "r"(bytes), "r"(mbar) : "memory");
}
#define MBAR_INIT(a,n)   asm volatile("mbarrier.init.shared.b64 [%0], %1;"::"r"(a),"r"(n):"memory")
#define MBAR_EXPECT(a,b) asm volatile("mbarrier.arrive.expect_tx.shared.b64 _, [%0], %1;"::"r"(a),"r"(b):"memory")
DI void mbwait(uint32_t mb, uint32_t par){
    uint32_t done;
    asm volatile("{\n\t.reg .pred p;\n\tmbarrier.try_wait.parity.acquire.cta.shared::cta.b64 p, [%1], %2;\n\tselp.b32 %0,1,0,p;\n\t}"
        :"=r"(done):"r"(mb),"r"(par):"memory");
    if(!done) asm volatile("{\n\t.reg .pred P1;\n\tWL_%=:\n\t"
        "mbarrier.try_wait.parity.acquire.cta.shared::cta.b64 P1, [%0], %1, 0x989680;\n\t"
        "@P1 bra.uni WD_%=;\n\tbra.uni WL_%=;\n\tWD_%=:\n\t}"::"r"(mb),"r"(par):"memory");
}

// tf32 slab mma for pv kernel (unchanged, proven)
DI void mma_slab(float (*acc)[16][4], const unsigned* Ab, const unsigned* Wb, int lane){
#pragma unroll
    for(int ks=0; ks<4; ks++){
        unsigned a[2][4];
#pragma unroll
        for(int mi=0; mi<2; mi++){
            int c0 = ks*8 + mi*2;
            a[mi][0]=Ab[(c0+0)*32+lane]; a[mi][1]=Ab[(c0+1)*32+lane];
            a[mi][2]=Ab[(c0+4)*32+lane]; a[mi][3]=Ab[(c0+5)*32+lane];
        }
        const uint4* bb = (const uint4*)(Wb + (ks*32+lane)*36);
#pragma unroll
        for(int jj=0; jj<8; jj++){
            uint4 b = bb[jj];
            mma8(acc[0][2*jj],  a[0][0],a[0][1],a[0][2],a[0][3],b.x,b.y);
            mma8(acc[1][2*jj],  a[1][0],a[1][1],a[1][2],a[1][3],b.x,b.y);
            mma8(acc[0][2*jj+1],a[0][0],a[0][1],a[0][2],a[0][3],b.z,b.w);
            mma8(acc[1][2*jj+1],a[1][0],a[1][1],a[1][2],a[1][3],b.z,b.w);
        }
    }
}

__global__ __launch_bounds__(256) void prep_kernel(
    const float* __restrict__ Wp, const float* __restrict__ bp,
    const float* __restrict__ Wv, const float* __restrict__ bv,
    const float* __restrict__ W1){
    __shared__ float Wc_s[32*128];
    __shared__ float Wr_s[16*128];
    int cb = blockIdx.x, isv = cb>=8, rb = (cb&7)*16;
    const float* Wx  = isv? Wv: Wp;
    const float* W1x = W1 + (isv? 128*128: 0);
    float* outW = isv? g_Wfv: g_Wfp;
    int t = threadIdx.x;
    for(int i=t; i<16*128; i+=256) Wr_s[i] = Wx[(rb+(i>>7))*128 + (i&127)];
    float acc[8];
#pragma unroll
    for(int ii=0; ii<8; ii++) acc[ii]=0.f;
    int j = t&127, ih = (t>>7)*8;
    for(int kc=0; kc<4; kc++){
        __syncthreads();
        for(int i=t; i<32*128; i+=256) Wc_s[i] = W1x[(kc*32+(i>>7))*128 + (i&127)];
        __syncthreads();
        for(int k=0; k<32; k++){
            float b = Wc_s[k*128+j];
#pragma unroll
            for(int ii=0; ii<8; ii++) acc[ii] += Wr_s[(ih+ii)*128 + kc*32+k]*b;
        }
    }
#pragma unroll
    for(int ii=0; ii<8; ii++) outW[(rb+ih+ii)*128 + j] = acc[ii];
    if((cb&7)==0 && t<128){
        const float* bx = isv? bv: bp;
        float s=0.f;
        for(int k=0;k<128;k++) s += bx[k]*W1x[k*128+t];
        g_biasF[isv*128+t] = s;
    }
}

__global__ __launch_bounds__(128) void pack_kernel(
    const float* __restrict__ Wp, const float* __restrict__ Wv){
    int sid = blockIdx.x;
    const float* src; unsigned* dst;
    if      (sid<4) { src = Wp + sid*32*128;          dst = g_Wpf  + sid*4608; }
    else if (sid<8) { src = g_Wfp + (sid-4)*32*128;   dst = g_Wfpf + (sid-4)*4608; }
    else if (sid<12){ src = Wv + (sid-8)*32*128;      dst = g_Wvf  + (sid-8)*4608; }
    else            { src = g_Wfv + (sid-12)*32*128;  dst = g_Wfvf + (sid-12)*4608; }
    int t=threadIdx.x, lane=t&31, ks=t>>5, gid=lane>>2, t4=lane&3;
#pragma unroll
    for(int j=0;j<16;j++)
#pragma unroll
        for(int r=0;r<2;r++)
            dst[(ks*32+lane)*36 + 2*j + r] = f2tf(src[(ks*8+t4+r*4)*128 + j*8 + gid]);
}

// fp16 fragment pack for main-kernel weights. grid 6 x 128.
__global__ __launch_bounds__(128) void pack16_kernel(
    const float* __restrict__ W1, const float* __restrict__ W2){
    int sid = blockIdx.x;
    const float* src; unsigned* dst;
    if(sid<4){ src = W1 + (256 + sid*64)*128; dst = g_W1h + sid*4608; }
    else     { src = W2 + (sid-4)*64*128;     dst = g_W2h + (sid-4)*4608; }
    int t=threadIdx.x, lane=t&31, ks=t>>5, gid=lane>>2, t4=lane&3;
#pragma unroll
    for(int j=0;j<16;j++)
#pragma unroll
        for(int r=0;r<2;r++){
            int k0 = ks*16 + 2*t4 + 8*r;
            dst[(ks*32+lane)*36 + 2*j + r] =
                pk2(src[k0*128 + 8*j + gid], src[(k0+1)*128 + 8*j + gid]);
        }
}

// pv: W slabs now via 2 bulk copies per slab (kills the LDGSTS flood).
// smem u32: W_s[0,9216) | A_f[9216,13312) | bias 13312..13568(f) | mbar@13568
__global__ __launch_bounds__(256) void pv_kernel(
    const float* __restrict__ price, const float* __restrict__ liquid,
    const float* __restrict__ bp, const float* __restrict__ bv){
    extern __shared__ float smpv[];
    unsigned* W_s = (unsigned*)smpv;
    unsigned* A_f = (unsigned*)smpv + 9216;
    float* bias_s = smpv + 13312;
    int cb=blockIdx.x, isv=cb>=64, rb=(cb&63)*128;
    const float* in = (isv? liquid: price) + (size_t)rb*128;
    const unsigned* pA = isv? g_Wvf : g_Wpf;
    const unsigned* pB = isv? g_Wfvf: g_Wfpf;
    float* outA = (isv? g_v : g_p)  + (size_t)rb*128;
    float* outB = (isv? g_V1: g_P1) + (size_t)rb*128;
    int t=threadIdx.x, w=t>>5, lane=t&31, gid=lane>>2, t4=lane&3;
    uint32_t Wsa = s2u(W_s);
    uint32_t mb  = Wsa + 13568*4;
    if(t==0) MBAR_INIT(mb, 1);
    if(t<128) bias_s[t] = isv? bv[t]: bp[t];
    else      bias_s[t] = g_biasF[isv*128 + (t-128)];
    int sub=((t&31)>>4)*2 + ((t&15)>>3), gid4=(t&7)*4, bgrp=(t>>5)*1024;
    int rowgrp=w&3, pk=w>>2;
    float acc[2][16][4];
#pragma unroll
    for(int mi=0;mi<2;mi++)
#pragma unroll
        for(int j=0;j<16;j++)
#pragma unroll
            for(int e=0;e<4;e++) acc[mi][j][e]=0.f;
    __syncthreads();   // mbar init visible
    for(int s=0;s<4;s++){
        if(s) __syncthreads();   // prior slab's W reads complete
        if(t==0){
            MBAR_EXPECT(mb, 36864);
            bulkcp(Wsa,        pA + s*4608, 18432, mb);
            bulkcp(Wsa+18432,  pB + s*4608, 18432, mb);
        }
        {   // build A fragments (t<128)
            if(t<128){
                const float4* row = (const float4*)(in + (size_t)t*128 + s*32);
#pragma unroll
                for(int g=0;g<8;g++){
                    float4 a=row[g];
                    uint4 o={f2tf(a.x),f2tf(a.y),f2tf(a.z),f2tf(a.w)};
                    *(uint4*)&A_f[bgrp + (g*4+sub)*32 + gid4] = o;
                }
            }
        }
        mbwait(mb, s&1);
        __syncthreads();   // publish A_f (and all passed the wait)
        mma_slab(acc, A_f + rowgrp*1024, W_s + pk*4608, lane);
    }
    float* outX = pk? outB: outA;
#pragma unroll
    for(int mi=0;mi<2;mi++){
        int r0 = rowgrp*32 + mi*16 + gid;
#pragma unroll
        for(int j=0;j<16;j++){
            int c=j*8+2*t4;
            float b0=bias_s[pk*128+c], b1=bias_s[pk*128+c+1];
            *(float2*)&outX[(size_t)r0*128+c]     = make_float2(acc[mi][j][0]+b0, acc[mi][j][1]+b1);
            *(float2*)&outX[(size_t)(r0+8)*128+c] = make_float2(acc[mi][j][2]+b0, acc[mi][j][3]+b1);
        }
    }
}

// A-fragment build for one k64 slab (s: 0/1 prod k0-63/k64-127, 2/3 absdiff).
// Base pointers pw/v0/v1 include the per-thread +2*t4 offset.
DI void buildA(unsigned ah[4][4], const float* pw, const float* v0, const float* v1, int s){
    const int kb0 = (s&1)*64;
    const float* pwk = pw + kb0;
    const float* v0k = v0 + kb0;
    const float* v1k = v1 + kb0;
#pragma unroll
    for(int ks=0;ks<4;ks++){
        int ko = ks*16;
        float2 pl = *(const float2*)&pwk[ko];
        float2 ph = *(const float2*)&pwk[ko+8];
        float2 a0=*(const float2*)&v0k[ko],   c0=*(const float2*)&v1k[ko];
        float2 a1=*(const float2*)&v0k[ko+8], c1=*(const float2*)&v1k[ko+8];
        if(s<2){
            ah[ks][0]=pk2(pl.x*a0.x, pl.y*a0.y);
            ah[ks][1]=pk2(pl.x*c0.x, pl.y*c0.y);
            ah[ks][2]=pk2(ph.x*a1.x, ph.y*a1.y);
            ah[ks][3]=pk2(ph.x*c1.x, ph.y*c1.y);
        }else{
            ah[ks][0]=pk2(fabsf(pl.x-a0.x), fabsf(pl.y-a0.y));
            ah[ks][1]=pk2(fabsf(pl.x-c0.x), fabsf(pl.y-c0.y));
            ah[ks][2]=pk2(fabsf(ph.x-a1.x), fabsf(ph.y-a1.y));
            ah[ks][3]=pk2(fabsf(ph.x-c1.x), fabsf(ph.y-c1.y));
        }
    }
}

DI void mmaW(float (*acc)[4], const unsigned ah[4][4], const unsigned* Wb, int lane){
#pragma unroll
    for(int ks=0;ks<4;ks++){
        const uint4* bb = (const uint4*)(Wb + (ks*32+lane)*36);
#pragma unroll
        for(int jj=0;jj<8;jj++){
            uint4 b = bb[jj];
            mma16(acc[2*jj],  ah[ks][0],ah[ks][1],ah[ks][2],ah[ks][3],b.x,b.y);
            mma16(acc[2*jj+1],ah[ks][0],ah[ks][1],ah[ks][2],ah[ks][3],b.z,b.w);
        }
    }
}

DI void mmaH(float (*acc)[4], const unsigned h2[16][2], int s2, const unsigned* Wb, int lane){
#pragma unroll
    for(int ks=0;ks<4;ks++){
        int kg = s2*4+ks;
        const uint4* bb = (const uint4*)(Wb + (ks*32+lane)*36);
#pragma unroll
        for(int jj=0;jj<8;jj++){
            uint4 b = bb[jj];
            mma16(acc[2*jj],  h2[2*kg][0],h2[2*kg][1],h2[2*kg+1][0],h2[2*kg+1][1],b.x,b.y);
            mma16(acc[2*jj+1],h2[2*kg][0],h2[2*kg][1],h2[2*kg+1][0],h2[2*kg+1][1],b.z,b.w);
        }
    }
}

// ---------------------------------------------------------------------------
// main v3 (fp16 m16n8k16), 256 thr / 8 warps — R10 math, bulk-copy loads.
// smem u32: Wbuf 4x4608 [0,18432) | b1@18432 b2@18560 | v@18688 (32x136) |
//   V1@23040 | p@27392 (4x136) | P1@27936..28480 | mbars@28480 (5x2)
// total 113960 B -> 2 CTAs/SM.  Slots: m0..m3 W ring (m0,m1 reused ph1), mt tiles.
// ---------------------------------------------------------------------------
__global__ __launch_bounds__(256,2) void pair_main_kernel(
    const float* __restrict__ b1v, const float* __restrict__ b2v,
    float* __restrict__ out){
    extern __shared__ float sm[];
    unsigned* Wbuf = (unsigned*)sm;
    float* b1_s = sm + 18432;
    float* b2_s = sm + 18560;
    float* v_s  = sm + 18688;
    float* V1_s = sm + 23040;
    float* p_s  = sm + 27392;
    float* P1_s = sm + 27936;
    const int bt=blockIdx.x>>3, pb=blockIdx.x&7;
    const int t=threadIdx.x, w=t>>5, lane=t&31;
    const int gid=lane>>2, t4=lane&3;
    const int n = w>>1, mbase = (w&1)*16;
    uint32_t Wba = s2u(Wbuf);
    uint32_t m0 = Wba + 28480*4;
    uint32_t m1 = m0+8, m2 = m0+16, m3 = m0+24, mt = m0+32;

    if(t==0){
        MBAR_INIT(m0,1); MBAR_INIT(m1,1); MBAR_INIT(m2,1);
        MBAR_INIT(m3,1); MBAR_INIT(mt,1);
    }
    __syncthreads();   // mbar init visible
    if(t==0){
        // W1 slabs 0-3 -> slots 0-3
        MBAR_EXPECT(m0,18432); bulkcp(Wba,         g_W1h,        18432, m0);
        MBAR_EXPECT(m1,18432); bulkcp(Wba+18432,   g_W1h+4608,   18432, m1);
        MBAR_EXPECT(m2,18432); bulkcp(Wba+2*18432, g_W1h+2*4608, 18432, m2);
        MBAR_EXPECT(m3,18432); bulkcp(Wba+3*18432, g_W1h+3*4608, 18432, m3);
        // tiles: v/V1 rows (padded stride 544B), p/P1 rows, biases
        MBAR_EXPECT(mt, 32*512*2 + 4*512*2 + 1024);
        uint32_t vA = s2u(v_s), vB = s2u(V1_s), pA = s2u(p_s), pB = s2u(P1_s);
        const float* vg  = g_v  + (size_t)bt*4096;
        const float* V1g = g_V1 + (size_t)bt*4096;
        for(int m=0;m<32;m++){
            bulkcp(vA + m*544, vg  + m*128, 512, mt);
            bulkcp(vB + m*544, V1g + m*128, 512, mt);
        }
        const float* pg  = g_p  + (size_t)(bt*32+pb*4)*128;
        const float* P1g = g_P1 + (size_t)(bt*32+pb*4)*128;
        for(int nn=0;nn<4;nn++){
            bulkcp(pA + nn*544, pg  + nn*128, 512, mt);
            bulkcp(pB + nn*544, P1g + nn*128, 512, mt);
        }
        bulkcp(s2u(b1_s), b1v, 512, mt);
        bulkcp(s2u(b2_s), b2v, 512, mt);
    }

    float acc[16][4];
#pragma unroll
    for(int j=0;j<16;j++)
#pragma unroll
        for(int e=0;e<4;e++) acc[j][e]=0.f;

    mbwait(mt, 0);   // tiles ready (every thread waits -> no barrier needed)
    const float* pw = p_s + n*136 + 2*t4;
    const float* v0 = v_s + (mbase+gid)*136 + 2*t4;
    const float* v1 = v0 + 8*136;

    unsigned ah[4][4];
    // slabs 0,1 (slots 0,1)
    buildA(ah, pw, v0, v1, 0);
    mbwait(m0, 0);
    mmaW(acc, ah, Wbuf, lane);
    buildA(ah, pw, v0, v1, 1);
    mbwait(m1, 0);
    mmaW(acc, ah, Wbuf+4608, lane);
    // refill slots 0,1 with W2 after ALL warps done with them
    __syncthreads();
    if(t==0){
        MBAR_EXPECT(m0,18432); bulkcp(Wba,       g_W2h,      18432, m0);
        MBAR_EXPECT(m1,18432); bulkcp(Wba+18432, g_W2h+4608, 18432, m1);
    }
    // slabs 2,3 (slots 2,3)
    buildA(ah, pw, v0, v1, 2);
    mbwait(m2, 0);
    mmaW(acc, ah, Wbuf+2*4608, lane);
    buildA(ah, pw, v0, v1, 3);
    mbwait(m3, 0);
    mmaW(acc, ah, Wbuf+3*4608, lane);

    // ------- epilogue 1: silu(D + P1 + V1 + b1) -> half2 regs (GEMM2 A) ----
    unsigned h2[16][2];
#pragma unroll
    for(int j=0;j<16;j++){
        int c0=j*8+2*t4;
        float2 P  =*(const float2*)&P1_s[n*136+c0];
        float2 Bb =*(const float2*)&b1_s[c0];
        float2 V0 =*(const float2*)&V1_s[(mbase+gid)*136+c0];
        float2 V1r=*(const float2*)&V1_s[(mbase+gid+8)*136+c0];
        float x0=acc[j][0]+P.x+V0.x+Bb.x;
        float x1=acc[j][1]+P.y+V0.y+Bb.y;
        float x2=acc[j][2]+P.x+V1r.x+Bb.x;
        float x3=acc[j][3]+P.y+V1r.y+Bb.y;
        x0=x0/(1.f+__expf(-x0)); x1=x1/(1.f+__expf(-x1));
        x2=x2/(1.f+__expf(-x2)); x3=x3/(1.f+__expf(-x3));
        h2[j][0]=pk2(x0,x1);
        h2[j][1]=pk2(x2,x3);
        acc[j][0]=0.f; acc[j][1]=0.f; acc[j][2]=0.f; acc[j][3]=0.f;
    }

    // ---- GEMM2: W2 slabs 0,1 (slots 0,1 phase 1), A from h2 regs ----
    mbwait(m0, 1);
    mmaH(acc, h2, 0, Wbuf, lane);
    mbwait(m1, 1);
    mmaH(acc, h2, 1, Wbuf+4608, lane);

    // ------------- epilogue 2: + b2, direct stores ----------------
    const size_t ob = (size_t)blockIdx.x*16384;
    float* o0 = out + ob + (size_t)(w*16+gid)*128;
    float* o1 = o0 + 1024;
#pragma unroll
    for(int j=0;j<16;j++){
        int c=j*8+2*t4;
        *(float2*)&o0[c] = make_float2(acc[j][0]+b2_s[c], acc[j][1]+b2_s[c+1]);
        *(float2*)&o1[c] = make_float2(acc[j][2]+b2_s[c], acc[j][3]+b2_s[c+1]);
    }
}

extern "C" void kernel_launch(void* const* d_in, const int* in_sizes, int n_in,
                              void* d_out, int out_size){
    const float* price =(const float*)d_in[0];
    const float* liquid=(const float*)d_in[1];
    const float* W_p=(const float*)d_in[2];
    const float* b_p=(const float*)d_in[3];
    const float* W_v=(const float*)d_in[4];
    const float* b_v=(const float*)d_in[5];
    const float* W1 =(const float*)d_in[6];
    const float* b1 =(const float*)d_in[7];
    const float* W2 =(const float*)d_in[8];
    const float* b2 =(const float*)d_in[9];
    float* out=(float*)d_out;
    cudaFuncSetAttribute(pv_kernel, cudaFuncAttributeMaxDynamicSharedMemorySize, 55296);
    cudaFuncSetAttribute(pair_main_kernel, cudaFuncAttributeMaxDynamicSharedMemorySize, 114688);
    prep_kernel<<<16, 256>>>(W_p, b_p, W_v, b_v, W1);
    pack_kernel<<<16, 128>>>(W_p, W_v);
    pack16_kernel<<<6, 128>>>(W1, W2);
    pv_kernel<<<128, 256, 54280>>>(price, liquid, b_p, b_v);
    pair_main_kernel<<<2048, 256, 113960>>>(b1, b2, out);
}